// round 4
// baseline (speedup 1.0000x reference)
#include <cuda_runtime.h>

#define DIMD  1024
#define NH    16
#define DH    64
#define BATCH 4
#define SEQ   2048
#define MTOT  (BATCH*SEQ)   // 8192

// Scratch (allocation-free rule: __device__ globals)
__device__ float g_Q[BATCH*NH*SEQ*DH];   // [B,H,S,Dh]
__device__ float g_K[BATCH*NH*SEQ*DH];
__device__ float g_V[BATCH*NH*SEQ*DH];
__device__ float g_A[MTOT*DIMD];         // attention output, [B,S,D]

__device__ __forceinline__ float f2tf32(float x) {
    unsigned u;
    asm("cvt.rna.tf32.f32 %0, %1;" : "=r"(u) : "f"(x));
    return __uint_as_float(u);
}

__device__ __forceinline__ void mma_tf32(
    float& c0, float& c1, float& c2, float& c3,
    unsigned a0, unsigned a1, unsigned a2, unsigned a3,
    unsigned b0, unsigned b1)
{
    asm volatile(
        "mma.sync.aligned.m16n8k8.row.col.f32.tf32.tf32.f32 "
        "{%0,%1,%2,%3}, {%4,%5,%6,%7}, {%8,%9}, {%0,%1,%2,%3};"
        : "+f"(c0), "+f"(c1), "+f"(c2), "+f"(c3)
        : "r"(a0), "r"(a1), "r"(a2), "r"(a3), "r"(b0), "r"(b1));
}

// ---------------------------------------------------------------------------
// TF32 GEMM, double-buffered SMEM, k-chunk 16, ONE barrier per iteration.
// Block tile 128x128, 8 warps (4Mx2N), warp tile 32x64.
// A stride 20 (20%32=20 -> frag banks 20*qr+qc distinct).
// B stride 132 (132%32=4 -> frag banks 4*qc+qr distinct).
// ---------------------------------------------------------------------------
#define AS_STRIDE 20
#define BS_STRIDE 132
#define AS_FLOATS (128*AS_STRIDE)   // 2560
#define BS_FLOATS (16*BS_STRIDE)    // 2112

template<int MODE>
__global__ __launch_bounds__(256, 2)
void gemm_tf32(const float* __restrict__ A, const float* __restrict__ B,
               const float* __restrict__ bias, float* __restrict__ out, int N)
{
    const int K = DIMD;
    __shared__ float As[2][AS_FLOATS];
    __shared__ float Bs[2][BS_FLOATS];

    const int tid  = threadIdx.x;
    const int lane = tid & 31;
    const int warp = tid >> 5;
    const int warp_m = warp & 3;
    const int warp_n = warp >> 2;
    const int qr = lane >> 2;
    const int qc = lane & 3;

    const int rowStart = blockIdx.y * 128;
    const int colStart = blockIdx.x * 128;
    const float* Ap = (MODE == 0) ? A : g_A;

    // per-thread load slots: A = 512 quads (128r x 4q), B = 512 quads (16r x 32q)
    const int ar0 = tid >> 1;              // A quad i: q=tid+i*256 -> row q>>2
    const int aq0 = (tid & 1) << 1;        //            colquad q&3
    const int br0 = tid >> 5;              // B quad i: row q>>5
    const int bq0 = tid & 31;              //            colquad q&31

    float acc[2][8][4];
    #pragma unroll
    for (int i = 0; i < 2; i++)
        #pragma unroll
        for (int j = 0; j < 8; j++)
            #pragma unroll
            for (int c = 0; c < 4; c++) acc[i][j][c] = 0.f;

    float4 av[2], bv[2];
    // prologue: chunk 0
    #pragma unroll
    for (int i = 0; i < 2; i++) {
        const int q = tid + i*256;
        av[i] = *(const float4*)(Ap + (long)(rowStart + (q>>2))*K + ((q&3)<<2));
        bv[i] = *(const float4*)(B + (long)(q>>5)*N + colStart + ((q&31)<<2));
    }
    #pragma unroll
    for (int i = 0; i < 2; i++) {
        const int q = tid + i*256;
        float* as = &As[0][(q>>2)*AS_STRIDE + ((q&3)<<2)];
        as[0]=f2tf32(av[i].x); as[1]=f2tf32(av[i].y);
        as[2]=f2tf32(av[i].z); as[3]=f2tf32(av[i].w);
        float* bs = &Bs[0][(q>>5)*BS_STRIDE + ((q&31)<<2)];
        bs[0]=f2tf32(bv[i].x); bs[1]=f2tf32(bv[i].y);
        bs[2]=f2tf32(bv[i].z); bs[3]=f2tf32(bv[i].w);
    }
    __syncthreads();

    const int NITER = K / 16;   // 64
    for (int it = 0; it < NITER; it++) {
        const int cur = it & 1, nxt = cur ^ 1;
        const bool more = (it + 1) < NITER;
        if (more) {
            const int k0 = (it + 1) << 4;
            #pragma unroll
            for (int i = 0; i < 2; i++) {
                const int q = tid + i*256;
                av[i] = *(const float4*)(Ap + (long)(rowStart + (q>>2))*K + k0 + ((q&3)<<2));
                bv[i] = *(const float4*)(B + (long)(k0 + (q>>5))*N + colStart + ((q&31)<<2));
            }
        }

        #pragma unroll
        for (int ks = 0; ks < 2; ks++) {
            const int kb = ks * 8;
            unsigned a[2][4], b[8][2];
            #pragma unroll
            for (int ma = 0; ma < 2; ma++) {
                const int r = warp_m*32 + ma*16 + qr;
                a[ma][0] = __float_as_uint(As[cur][(r    )*AS_STRIDE + kb + qc    ]);
                a[ma][1] = __float_as_uint(As[cur][(r + 8)*AS_STRIDE + kb + qc    ]);
                a[ma][2] = __float_as_uint(As[cur][(r    )*AS_STRIDE + kb + qc + 4]);
                a[ma][3] = __float_as_uint(As[cur][(r + 8)*AS_STRIDE + kb + qc + 4]);
            }
            #pragma unroll
            for (int nb = 0; nb < 8; nb++) {
                const int cc = warp_n*64 + nb*8 + qr;
                b[nb][0] = __float_as_uint(Bs[cur][(kb + qc    )*BS_STRIDE + cc]);
                b[nb][1] = __float_as_uint(Bs[cur][(kb + qc + 4)*BS_STRIDE + cc]);
            }
            #pragma unroll
            for (int ma = 0; ma < 2; ma++)
                #pragma unroll
                for (int nb = 0; nb < 8; nb++)
                    mma_tf32(acc[ma][nb][0], acc[ma][nb][1],
                             acc[ma][nb][2], acc[ma][nb][3],
                             a[ma][0], a[ma][1], a[ma][2], a[ma][3],
                             b[nb][0], b[nb][1]);
        }

        if (more) {
            #pragma unroll
            for (int i = 0; i < 2; i++) {
                const int q = tid + i*256;
                float* as = &As[nxt][(q>>2)*AS_STRIDE + ((q&3)<<2)];
                as[0]=f2tf32(av[i].x); as[1]=f2tf32(av[i].y);
                as[2]=f2tf32(av[i].z); as[3]=f2tf32(av[i].w);
                float* bs = &Bs[nxt][(q>>5)*BS_STRIDE + ((q&31)<<2)];
                bs[0]=f2tf32(bv[i].x); bs[1]=f2tf32(bv[i].y);
                bs[2]=f2tf32(bv[i].z); bs[3]=f2tf32(bv[i].w);
            }
            __syncthreads();
        }
    }

    #pragma unroll
    for (int ma = 0; ma < 2; ma++) {
        const int row0 = rowStart + warp_m*32 + ma*16 + qr;
        #pragma unroll
        for (int nb = 0; nb < 8; nb++) {
            const int col = colStart + warp_n*64 + nb*8 + qc*2;
            const float b0 = bias[col], b1 = bias[col + 1];
            float2 v0 = make_float2(acc[ma][nb][0] + b0, acc[ma][nb][1] + b1);
            float2 v1 = make_float2(acc[ma][nb][2] + b0, acc[ma][nb][3] + b1);
            if (MODE == 0) {
                const int part = col >> 10;
                const int dcol = col & 1023;
                const int head = dcol >> 6;
                const int dh   = dcol & 63;
                float* dst = (part == 0) ? g_Q : (part == 1) ? g_K : g_V;
                {
                    const int bb = row0 >> 11, s = row0 & 2047;
                    *(float2*)(dst + (((bb*NH + head)*SEQ + s) << 6) + dh) = v0;
                }
                {
                    const int row1 = row0 + 8;
                    const int bb = row1 >> 11, s = row1 & 2047;
                    *(float2*)(dst + (((bb*NH + head)*SEQ + s) << 6) + dh) = v1;
                }
            } else {
                *(float2*)(out + (long)row0*N + col) = v0;
                *(float2*)(out + (long)(row0 + 8)*N + col) = v1;
            }
        }
    }
}

// ---------------------------------------------------------------------------
// TF32 tensor-core flash attention with hoisted K/V global loads.
// ---------------------------------------------------------------------------
#define QS_OFF 0
#define KS_OFF 8704               // 128*68
#define VT_OFF 13056              // + 64*68
#define PS_OFF 17408              // + 64*68
#define ATTN_SMEM_FLOATS 26112    // + 128*68
#define ATTN_SMEM_BYTES (ATTN_SMEM_FLOATS*4)   // 104448

__global__ __launch_bounds__(256, 2)
void attn_tf32()
{
    extern __shared__ float sm[];
    float* Qs = sm + QS_OFF;   // [128][68]
    float* Ks = sm + KS_OFF;   // [64][68]
    float* Vt = sm + VT_OFF;   // [64][68]  (transposed V)
    float* Ps = sm + PS_OFF;   // [128][68]

    const int tid  = threadIdx.x;
    const int lane = tid & 31;
    const int warp = tid >> 5;
    const int qr = lane >> 2;
    const int qc = lane & 3;

    const int qt = (int)(gridDim.x - 1) - (int)blockIdx.x;
    const int h = blockIdx.y, b = blockIdx.z;
    const int q0 = qt << 7;

    const long hb = (long)(b*NH + h) * SEQ * DH;
    const float* Qg = g_Q + hb;
    const float* Kg = g_K + hb;
    const float* Vg = g_V + hb;

    #pragma unroll
    for (int i = 0; i < 8; i++) {
        const int q = tid + i*256;
        const int r = q >> 4, dq = (q & 15) << 2;
        float4 t = *(const float4*)(Qg + (q0 + r)*DH + dq);
        float4 c;
        c.x = f2tf32(t.x * 0.125f); c.y = f2tf32(t.y * 0.125f);
        c.z = f2tf32(t.z * 0.125f); c.w = f2tf32(t.w * 0.125f);
        *(float4*)(Qs + r*68 + dq) = c;
    }

    float m0 = -1e30f, m1 = -1e30f, l0 = 0.f, l1 = 0.f;
    float o[8][4];
    #pragma unroll
    for (int nb = 0; nb < 8; nb++)
        #pragma unroll
        for (int c = 0; c < 4; c++) o[nb][c] = 0.f;

    const int rowA = warp*16 + qr;
    const int ktiles = 2*qt + 2;
    const int vkey = tid & 63;
    const int vdq0 = (tid >> 6) << 2;

    for (int kt = 0; kt < ktiles; kt++) {
        const int k0 = kt << 6;

        // hoisted global loads (overlap prior PV compute / barrier wait)
        float4 kreg[4], vreg[4];
        #pragma unroll
        for (int i = 0; i < 4; i++) {
            const int q = tid + i*256;
            kreg[i] = *(const float4*)(Kg + (k0 + (q>>4))*DH + ((q&15)<<2));
            vreg[i] = *(const float4*)(Vg + (k0 + vkey)*DH + vdq0 + i*16);
        }

        __syncthreads();   // prior PV reads of Vt/Ps done; Q visible (iter 0)

        #pragma unroll
        for (int i = 0; i < 4; i++) {
            const int q = tid + i*256;
            const int r = q >> 4, dq = (q & 15) << 2;
            float* ks = Ks + r*68 + dq;
            ks[0]=f2tf32(kreg[i].x); ks[1]=f2tf32(kreg[i].y);
            ks[2]=f2tf32(kreg[i].z); ks[3]=f2tf32(kreg[i].w);
            const int dq2 = vdq0 + i*16;
            Vt[(dq2+0)*68 + vkey] = f2tf32(vreg[i].x);
            Vt[(dq2+1)*68 + vkey] = f2tf32(vreg[i].y);
            Vt[(dq2+2)*68 + vkey] = f2tf32(vreg[i].z);
            Vt[(dq2+3)*68 + vkey] = f2tf32(vreg[i].w);
        }
        __syncthreads();

        float sv[8][4];
        #pragma unroll
        for (int nb = 0; nb < 8; nb++)
            #pragma unroll
            for (int c = 0; c < 4; c++) sv[nb][c] = 0.f;

        #pragma unroll
        for (int ks = 0; ks < 8; ks++) {
            const int kb = ks*8;
            const unsigned a0 = __float_as_uint(Qs[(rowA    )*68 + kb+qc  ]);
            const unsigned a1 = __float_as_uint(Qs[(rowA + 8)*68 + kb+qc  ]);
            const unsigned a2 = __float_as_uint(Qs[(rowA    )*68 + kb+qc+4]);
            const unsigned a3 = __float_as_uint(Qs[(rowA + 8)*68 + kb+qc+4]);
            #pragma unroll
            for (int nb = 0; nb < 8; nb++) {
                const unsigned b0 = __float_as_uint(Ks[(nb*8+qr)*68 + kb+qc  ]);
                const unsigned b1 = __float_as_uint(Ks[(nb*8+qr)*68 + kb+qc+4]);
                mma_tf32(sv[nb][0], sv[nb][1], sv[nb][2], sv[nb][3],
                         a0, a1, a2, a3, b0, b1);
            }
        }

        if (kt >= 2*qt) {
            const int qg0 = q0 + rowA;
            #pragma unroll
            for (int nb = 0; nb < 8; nb++) {
                const int kg = k0 + nb*8 + 2*qc;
                if (kg     > qg0    ) sv[nb][0] = -1e30f;
                if (kg + 1 > qg0    ) sv[nb][1] = -1e30f;
                if (kg     > qg0 + 8) sv[nb][2] = -1e30f;
                if (kg + 1 > qg0 + 8) sv[nb][3] = -1e30f;
            }
        }

        float mx0 = -1e30f, mx1 = -1e30f;
        #pragma unroll
        for (int nb = 0; nb < 8; nb++) {
            mx0 = fmaxf(mx0, fmaxf(sv[nb][0], sv[nb][1]));
            mx1 = fmaxf(mx1, fmaxf(sv[nb][2], sv[nb][3]));
        }
        mx0 = fmaxf(mx0, __shfl_xor_sync(0xffffffffu, mx0, 1));
        mx0 = fmaxf(mx0, __shfl_xor_sync(0xffffffffu, mx0, 2));
        mx1 = fmaxf(mx1, __shfl_xor_sync(0xffffffffu, mx1, 1));
        mx1 = fmaxf(mx1, __shfl_xor_sync(0xffffffffu, mx1, 2));

        const float m0n = fmaxf(m0, mx0);
        const float m1n = fmaxf(m1, mx1);
        const float al0 = __expf(m0 - m0n);
        const float al1 = __expf(m1 - m1n);
        m0 = m0n; m1 = m1n;

        float ps0 = 0.f, ps1 = 0.f;
        #pragma unroll
        for (int nb = 0; nb < 8; nb++) {
            sv[nb][0] = __expf(sv[nb][0] - m0n);
            sv[nb][1] = __expf(sv[nb][1] - m0n);
            sv[nb][2] = __expf(sv[nb][2] - m1n);
            sv[nb][3] = __expf(sv[nb][3] - m1n);
            ps0 += sv[nb][0] + sv[nb][1];
            ps1 += sv[nb][2] + sv[nb][3];
        }
        ps0 += __shfl_xor_sync(0xffffffffu, ps0, 1);
        ps0 += __shfl_xor_sync(0xffffffffu, ps0, 2);
        ps1 += __shfl_xor_sync(0xffffffffu, ps1, 1);
        ps1 += __shfl_xor_sync(0xffffffffu, ps1, 2);
        l0 = l0*al0 + ps0;
        l1 = l1*al1 + ps1;
        #pragma unroll
        for (int nb = 0; nb < 8; nb++) {
            o[nb][0] *= al0; o[nb][1] *= al0;
            o[nb][2] *= al1; o[nb][3] *= al1;
        }

        #pragma unroll
        for (int nb = 0; nb < 8; nb++) {
            const int kc = nb*8 + 2*qc;
            *(float2*)(Ps + (rowA    )*68 + kc) =
                make_float2(f2tf32(sv[nb][0]), f2tf32(sv[nb][1]));
            *(float2*)(Ps + (rowA + 8)*68 + kc) =
                make_float2(f2tf32(sv[nb][2]), f2tf32(sv[nb][3]));
        }
        __syncthreads();

        #pragma unroll
        for (int ks = 0; ks < 8; ks++) {
            const int kb = ks*8;
            const unsigned a0 = __float_as_uint(Ps[(rowA    )*68 + kb+qc  ]);
            const unsigned a1 = __float_as_uint(Ps[(rowA + 8)*68 + kb+qc  ]);
            const unsigned a2 = __float_as_uint(Ps[(rowA    )*68 + kb+qc+4]);
            const unsigned a3 = __float_as_uint(Ps[(rowA + 8)*68 + kb+qc+4]);
            #pragma unroll
            for (int nb = 0; nb < 8; nb++) {
                const unsigned b0 = __float_as_uint(Vt[(nb*8+qr)*68 + kb+qc  ]);
                const unsigned b1 = __float_as_uint(Vt[(nb*8+qr)*68 + kb+qc+4]);
                mma_tf32(o[nb][0], o[nb][1], o[nb][2], o[nb][3],
                         a0, a1, a2, a3, b0, b1);
            }
        }
    }

    const float inv0 = 1.0f / l0;
    const float inv1 = 1.0f / l1;
    const long r0 = (long)(b*SEQ + q0 + rowA);
    #pragma unroll
    for (int nb = 0; nb < 8; nb++) {
        const int col = h*DH + nb*8 + 2*qc;
        *(float2*)(g_A + r0*DIMD + col) =
            make_float2(o[nb][0]*inv0, o[nb][1]*inv0);
        *(float2*)(g_A + (r0 + 8)*DIMD + col) =
            make_float2(o[nb][2]*inv1, o[nb][3]*inv1);
    }
}

// ---------------------------------------------------------------------------
extern "C" void kernel_launch(void* const* d_in, const int* in_sizes, int n_in,
                              void* d_out, int out_size)
{
    const float* x      = (const float*)d_in[0];
    const float* w_qkv  = (const float*)d_in[1];
    const float* b_qkv  = (const float*)d_in[2];
    const float* w_proj = (const float*)d_in[3];
    const float* b_proj = (const float*)d_in[4];
    float* out = (float*)d_out;

    cudaFuncSetAttribute(attn_tf32,
        cudaFuncAttributeMaxDynamicSharedMemorySize, ATTN_SMEM_BYTES);

    gemm_tf32<0><<<dim3(3*DIMD/128, MTOT/128), 256>>>(x, w_qkv, b_qkv, nullptr, 3*DIMD);
    attn_tf32<<<dim3(SEQ/128, NH, BATCH), 256, ATTN_SMEM_BYTES>>>();
    gemm_tf32<1><<<dim3(DIMD/128, MTOT/128), 256>>>(nullptr, w_proj, b_proj, out, DIMD);
}